// round 13
// baseline (speedup 1.0000x reference)
#include <cuda_runtime.h>
#include <math.h>

// Problem dims
#define T_    512
#define B_    64
#define F_    256
#define E_    512
#define G4E   2048   // 4*E
#define G4F   1024   // 4*F
#define DECIN 1024   // 2*E

typedef unsigned long long u64;

// ---------------- device scratch (static; no allocations) ----------------
__device__ float g_xproj[2][T_][B_][G4E];     // [dir][t][b][col], col = u*4+gate
__device__ float g_WihIl[2][G4E][F_];         // interleaved enc Wih (rows = u*4+g)
__device__ float g_bIl[2][G4E];
__device__ float g_WhhIl[2][E_][E_][4];       // [dir][u][k][gate]
__device__ float g_h[2][2][E_][B_];           // [dir][phase][u][b]  ping-pong
__device__ float g_WdecIhIl[F_][DECIN][4];    // [f][k][gate]
__device__ float g_bdecIl[F_][4];
__device__ u64   g_WdecHhDup[F_][F_][4];      // [f][k][gate] duplicated {w,w}
__device__ float g_hd[2][F_][B_];             // decoder h ping-pong
__device__ unsigned g_cnt[2][32];             // enc barrier counters (padded per dir)
__device__ unsigned g_cntd[32];               // dec barrier counter

__device__ __forceinline__ float sigm(float x) {
    return __fdividef(1.0f, 1.0f + __expf(-x));
}
__device__ __forceinline__ float tanh_f(float x) {
    float ax = fabsf(x);
    float e = __expf(-2.0f * ax);
    float r = (1.0f - e) * __fdividef(1.0f, 1.0f + e);
    return copysignf(r, x);
}

__device__ __forceinline__ u64 dup2(float x) {
    u64 r; asm("mov.b64 %0, {%1, %1};" : "=l"(r) : "f"(x)); return r;
}
__device__ __forceinline__ void fma2(u64& d, u64 a, u64 b) {
    asm("fma.rn.f32x2 %0, %1, %2, %0;" : "+l"(d) : "l"(a), "l"(b));
}
__device__ __forceinline__ u64 add2(u64 a, u64 b) {
    u64 r; asm("add.rn.f32x2 %0, %1, %2;" : "=l"(r) : "l"(a), "l"(b)); return r;
}
__device__ __forceinline__ float2 unpk(u64 v) {
    float2 r; asm("mov.b64 {%0, %1}, %2;" : "=f"(r.x), "=f"(r.y) : "l"(v)); return r;
}
__device__ __forceinline__ unsigned ld_acquire(unsigned* p) {
    unsigned v;
    asm volatile("ld.acquire.gpu.global.u32 %0, [%1];" : "=r"(v) : "l"(p) : "memory");
    return v;
}
__device__ __forceinline__ void red_release(unsigned* p, unsigned v) {
    asm volatile("red.release.gpu.global.add.u32 [%0], %1;" :: "l"(p), "r"(v) : "memory");
}
__device__ __forceinline__ u64 ldcg8(const void* p) {
    u64 v;
    asm volatile("ld.global.cg.u64 %0, [%1];" : "=l"(v) : "l"(p));
    return v;
}
__device__ __forceinline__ void cp16(void* sdst, const void* gsrc) {
    unsigned s = (unsigned)__cvta_generic_to_shared(sdst);
    asm volatile("cp.async.cg.shared.global [%0], [%1], 16;" :: "r"(s), "l"(gsrc) : "memory");
}
__device__ __forceinline__ void cp_commit() { asm volatile("cp.async.commit_group;" ::: "memory"); }
template<int N> __device__ __forceinline__ void cp_wait() {
    asm volatile("cp.async.wait_group %0;" :: "n"(N) : "memory");
}
__device__ __forceinline__ void bar_named(int id, int cnt) {
    asm volatile("bar.sync %0, %1;" :: "r"(id), "r"(cnt) : "memory");
}

// ---------------- probe: keeps ncu's captured position stable ----------------
__global__ void probe_kernel() {}

// ---------------- prep: interleave weights, zero states ----------------
__global__ void prep_kernel(const float* wihf, const float* whhf, const float* bf,
                            const float* wihb, const float* whhb, const float* bb,
                            const float* dwih, const float* dwhh, const float* db)
{
    int tid = blockIdx.x * blockDim.x + threadIdx.x;
    int stride = gridDim.x * blockDim.x;

    // enc Wih interleave: [2][2048][256]
    for (int i = tid; i < 2 * G4E * F_; i += stride) {
        int d = i / (G4E * F_);
        int r = i - d * (G4E * F_);
        int col = r / F_;
        int k = r - col * F_;
        int u = col >> 2, g = col & 3;
        const float* src = d ? wihb : wihf;
        g_WihIl[d][col][k] = src[(g * E_ + u) * F_ + k];
    }
    // enc bias interleave
    for (int i = tid; i < 2 * G4E; i += stride) {
        int d = i >> 11, col = i & (G4E - 1);
        int u = col >> 2, g = col & 3;
        g_bIl[d][col] = (d ? bb : bf)[g * E_ + u];
    }
    // enc Whh interleave: [2][512][512][4]
    for (int i = tid; i < 2 * E_ * E_ * 4; i += stride) {
        int d = i / (E_ * E_ * 4);
        int r = i - d * (E_ * E_ * 4);
        int u = r / (E_ * 4);
        int k = (r >> 2) & (E_ - 1);
        int g = r & 3;
        g_WhhIl[d][u][k][g] = (d ? whhb : whhf)[(g * E_ + u) * E_ + k];
    }
    // dec Wih interleave: [256][1024][4]
    for (int i = tid; i < F_ * DECIN * 4; i += stride) {
        int f = i / (DECIN * 4);
        int k = (i >> 2) & (DECIN - 1);
        int g = i & 3;
        g_WdecIhIl[f][k][g] = dwih[(g * F_ + f) * DECIN + k];
    }
    for (int i = tid; i < G4F; i += stride) {
        int f = i >> 2, g = i & 3;
        g_bdecIl[f][g] = db[g * F_ + f];
    }
    // dec Whh duplicated: [256][256][4] u64
    for (int i = tid; i < F_ * F_ * 4; i += stride) {
        int f = i / (F_ * 4);
        int k = (i >> 2) & (F_ - 1);
        int g = i & 3;
        float v = dwhh[(g * F_ + f) * F_ + k];
        unsigned bits = __float_as_uint(v);
        g_WdecHhDup[f][k][g] = ((u64)bits << 32) | (u64)bits;
    }
    // zero states + counters
    for (int i = tid; i < 2 * 2 * E_ * B_; i += stride) ((float*)g_h)[i] = 0.0f;
    for (int i = tid; i < 2 * F_ * B_; i += stride)     ((float*)g_hd)[i] = 0.0f;
    if (tid < 64) ((unsigned*)g_cnt)[tid] = 0u;
    if (tid < 32) g_cntd[tid] = 0u;
}

// ---------------- xproj GEMM: M=32768, N=2048, K=256 ----------------
// Register double-buffer: next tile's LDG issued right after sync, hidden under compute.
__global__ void __launch_bounds__(256, 1) xproj_gemm(const float* __restrict__ seq)
{
    const int dir = blockIdx.z;
    const int m0 = blockIdx.y * 128;
    const int n0 = blockIdx.x * 128;
    const int tid = threadIdx.x;
    const int ty = tid >> 4;
    const int tx = tid & 15;

    __shared__ float As[16][128];
    __shared__ float Bs[16][128];

    u64 acc[8][4];
#pragma unroll
    for (int i = 0; i < 8; i++)
#pragma unroll
        for (int j = 0; j < 4; j++) acc[i][j] = 0ull;

    const float* W = &g_WihIl[dir][0][0];

    // per-thread A/B load coordinates (fixed across k0)
    int arow[2], akq[2], nidx[2], bkq[2];
    const float* aptr[2];
#pragma unroll
    for (int p = 0; p < 2; p++) {
        int idx = tid + p * 256;
        arow[p] = idx >> 2; akq[p] = idx & 3;
        int m = m0 + arow[p];
        int tt = m >> 6, b = m & 63;
        int ts = dir ? (T_ - 1 - tt) : tt;
        aptr[p] = &seq[((size_t)ts * B_ + b) * F_];
        nidx[p] = idx >> 2; bkq[p] = idx & 3;
    }

    float4 ra[2], rb[2];
#pragma unroll
    for (int p = 0; p < 2; p++) {
        ra[p] = *(const float4*)&aptr[p][akq[p] * 4];
        rb[p] = *(const float4*)&W[(size_t)(n0 + nidx[p]) * F_ + bkq[p] * 4];
    }

    for (int k0 = 0; k0 < F_; k0 += 16) {
        // store current tile
#pragma unroll
        for (int p = 0; p < 2; p++) {
            As[akq[p] * 4 + 0][arow[p]] = ra[p].x;
            As[akq[p] * 4 + 1][arow[p]] = ra[p].y;
            As[akq[p] * 4 + 2][arow[p]] = ra[p].z;
            As[akq[p] * 4 + 3][arow[p]] = ra[p].w;
            Bs[bkq[p] * 4 + 0][nidx[p]] = rb[p].x;
            Bs[bkq[p] * 4 + 1][nidx[p]] = rb[p].y;
            Bs[bkq[p] * 4 + 2][nidx[p]] = rb[p].z;
            Bs[bkq[p] * 4 + 3][nidx[p]] = rb[p].w;
        }
        __syncthreads();

        // prefetch next tile (latency hidden under compute below)
        if (k0 + 16 < F_) {
#pragma unroll
            for (int p = 0; p < 2; p++) {
                ra[p] = *(const float4*)&aptr[p][k0 + 16 + akq[p] * 4];
                rb[p] = *(const float4*)&W[(size_t)(n0 + nidx[p]) * F_ + k0 + 16 + bkq[p] * 4];
            }
        }

#pragma unroll
        for (int kk = 0; kk < 16; kk++) {
            float4 a0 = *(const float4*)&As[kk][ty * 8];
            float4 a1 = *(const float4*)&As[kk][ty * 8 + 4];
            ulonglong2 bA = *(const ulonglong2*)&Bs[kk][tx * 4];
            ulonglong2 bB = *(const ulonglong2*)&Bs[kk][64 + tx * 4];
            float av[8] = {a0.x, a0.y, a0.z, a0.w, a1.x, a1.y, a1.z, a1.w};
#pragma unroll
            for (int i = 0; i < 8; i++) {
                u64 ad = dup2(av[i]);
                fma2(acc[i][0], ad, bA.x);
                fma2(acc[i][1], ad, bA.y);
                fma2(acc[i][2], ad, bB.x);
                fma2(acc[i][3], ad, bB.y);
            }
        }
        __syncthreads();
    }

    float4 bias0 = *(const float4*)&g_bIl[dir][n0 + tx * 4];
    float4 bias1 = *(const float4*)&g_bIl[dir][n0 + 64 + tx * 4];
    float* out = &g_xproj[0][0][0][0];
#pragma unroll
    for (int i = 0; i < 8; i++) {
        size_t m = (size_t)m0 + ty * 8 + i;
        size_t base = ((size_t)dir * 32768 + m) * (size_t)G4E + n0;
        float2 c0 = unpk(acc[i][0]), c1 = unpk(acc[i][1]);
        float2 c2 = unpk(acc[i][2]), c3 = unpk(acc[i][3]);
        float4 o0 = {c0.x + bias0.x, c0.y + bias0.y, c1.x + bias0.z, c1.y + bias0.w};
        float4 o1 = {c2.x + bias1.x, c2.y + bias1.y, c3.x + bias1.z, c3.y + bias1.w};
        *(float4*)&out[base + tx * 4] = o0;
        *(float4*)&out[base + 64 + tx * 4] = o1;
    }
}

// ---------------- persistent encoder ----------------
// 128 CTAs (64/dir, 8 units each), 256 threads = 8 warps (2/SMSP for latency hiding).
// Warp = (k-quarter, unit-half); thread = 1 unit x 8 batches (acc = 32 regs).
#define ENC_HS_OFF  65536                    // ws: 512*8 float4 = 64KB
#define ENC_XCH_OFF (65536 + 131072)         // hs: 512*64 floats = 128KB
#define ENC_XPS_OFF (ENC_XCH_OFF + 24576)    // xch: u64[3][16][64] = 24KB
#define ENC_SMEM    (ENC_XPS_OFF + 8192)     // xps: float4[64][8] = 8KB -> 229376

__global__ void __launch_bounds__(256, 1) enc_persist()
{
    extern __shared__ char smraw[];
    float4* wsP = (float4*)smraw;                    // [k][8 units]
    float*  hs  = (float*)(smraw + ENC_HS_OFF);      // [512][64]
    u64*    xch = (u64*)(smraw + ENC_XCH_OFF);       // [3][16 elems][64 slots]
    float4* xps = (float4*)(smraw + ENC_XPS_OFF);    // [64 b][8 u]

    const int dir = (int)(blockIdx.x >> 6);
    const int u0  = (int)(blockIdx.x & 63) * 8;
    const int tid = threadIdx.x;
    const int w   = tid >> 5;
    const int ks  = w >> 1;            // k-quarter 0..3
    const int uh  = w & 1;             // unit half 0..1
    const int l   = tid & 31;
    const int u   = uh * 4 + (l >> 3); // local unit 0..7
    const int b0  = (l & 7) * 8;       // 8 batches
    const int s   = uh * 32 + l;       // slot within quarter 0..63

    // load Whh slice once, transposed to k-major [k][u]
    {
        const float4* src = (const float4*)&g_WhhIl[dir][u0][0][0];
        for (int i = tid; i < 4096; i += 256)
            wsP[i] = src[(i & 7) * 512 + (i >> 3)];
    }
    __syncthreads();

    unsigned* cnt = &g_cnt[dir][0];
    float c[8];
#pragma unroll
    for (int j = 0; j < 8; j++) c[j] = 0.0f;

    // stage xproj for t=0
    for (int i = tid; i < 512; i += 256)
        cp16(&xps[i], &g_xproj[dir][0][i >> 3][(u0 + (i & 7)) << 2]);
    cp_commit();

    for (int t = 0; t < T_; t++) {
        const int ph = t & 1;

        // wait for h(t-1) from all CTAs of this dir
        if (t > 0) {
            if (tid < 32) {
                const unsigned tgt = (unsigned)t * 64u;
                while (ld_acquire(cnt) < tgt) {}
            }
            __syncthreads();
        }

        const int kbase = ks * 128;

        // stage this quarter (2048 float4) cooperatively by its 2 warps, 2 halves
        {
            const float4* hsrc = (const float4*)&g_h[dir][ph][kbase][0];
            float4* hdst = (float4*)&hs[kbase * 64];
            for (int i = s; i < 1024; i += 64) cp16(hdst + i, hsrc + i);
            cp_commit();
            for (int i = s + 1024; i < 2048; i += 64) cp16(hdst + i, hsrc + i);
            cp_commit();
        }
        // pending groups: [xps][h1][h2]

        u64 acc[4][4];
#pragma unroll
        for (int g = 0; g < 4; g++)
#pragma unroll
            for (int p = 0; p < 4; p++) acc[g][p] = 0ull;

#pragma unroll
        for (int half = 0; half < 2; half++) {
            if (half == 0) cp_wait<1>(); else cp_wait<0>();
            bar_named(1 + ks, 64);   // both warps of this quarter see full staged half
            const int kst = kbase + half * 64;
#pragma unroll 4
            for (int kk = 0; kk < 64; kk++) {
                const int k = kst + kk;
                float4 wv = wsP[k * 8 + u];
                const ulonglong2* hp = (const ulonglong2*)(hs + k * 64 + b0);
                ulonglong2 hA = hp[0], hB = hp[1];
                u64 d0 = dup2(wv.x), d1 = dup2(wv.y), d2 = dup2(wv.z), d3 = dup2(wv.w);
                fma2(acc[0][0], hA.x, d0); fma2(acc[0][1], hA.y, d0);
                fma2(acc[0][2], hB.x, d0); fma2(acc[0][3], hB.y, d0);
                fma2(acc[1][0], hA.x, d1); fma2(acc[1][1], hA.y, d1);
                fma2(acc[1][2], hB.x, d1); fma2(acc[1][3], hB.y, d1);
                fma2(acc[2][0], hA.x, d2); fma2(acc[2][1], hA.y, d2);
                fma2(acc[2][2], hB.x, d2); fma2(acc[2][3], hB.y, d2);
                fma2(acc[3][0], hA.x, d3); fma2(acc[3][1], hA.y, d3);
                fma2(acc[3][2], hB.x, d3); fma2(acc[3][3], hB.y, d3);
            }
        }

        // publish partials (transposed: element-major, slot contiguous)
        if (ks > 0) {
            u64* dst = xch + (size_t)(ks - 1) * 16 * 64 + s;
#pragma unroll
            for (int g = 0; g < 4; g++)
#pragma unroll
                for (int p = 0; p < 4; p++)
                    dst[(g * 4 + p) * 64] = acc[g][p];
        }
        __syncthreads();

        if (ks == 0) {
            const u64* src0 = xch + s;
#pragma unroll
            for (int r = 0; r < 3; r++) {
                const u64* src = src0 + (size_t)r * 16 * 64;
#pragma unroll
                for (int g = 0; g < 4; g++)
#pragma unroll
                    for (int p = 0; p < 4; p++)
                        acc[g][p] = add2(acc[g][p], src[(g * 4 + p) * 64]);
            }
            float hv[8];
#pragma unroll
            for (int p = 0; p < 4; p++) {
                float2 iv = unpk(acc[0][p]);
                float2 fv = unpk(acc[1][p]);
                float2 gv = unpk(acc[2][p]);
                float2 ov = unpk(acc[3][p]);
#pragma unroll
                for (int q = 0; q < 2; q++) {
                    int j = p * 2 + q;
                    float4 xv = xps[(b0 + j) * 8 + u];
                    float iq = q ? iv.y : iv.x;
                    float fq = q ? fv.y : fv.x;
                    float gq = q ? gv.y : gv.x;
                    float oq = q ? ov.y : ov.x;
                    float ig = sigm(iq + xv.x);
                    float fg = sigm(fq + xv.y);
                    float gg = tanh_f(gq + xv.z);
                    float og = sigm(oq + xv.w);
                    c[j] = fg * c[j] + ig * gg;
                    hv[j] = og * tanh_f(c[j]);
                }
            }
            float* hout = &g_h[dir][ph ^ 1][u0 + u][b0];
            *(float4*)(hout)     = make_float4(hv[0], hv[1], hv[2], hv[3]);
            *(float4*)(hout + 4) = make_float4(hv[4], hv[5], hv[6], hv[7]);
        }
        __syncthreads();

        // arrive; then stage next step's xproj (independent of barrier)
        if (tid == 0) red_release(cnt, 1u);
        if (t + 1 < T_) {
            for (int i = tid; i < 512; i += 256)
                cp16(&xps[i], &g_xproj[dir][t + 1][i >> 3][(u0 + (i & 7)) << 2]);
            cp_commit();
        }
    }
}

// ---------------- persistent decoder (xp0 fused) ----------------
#define DEC_XCH_OFF 16384
#define DEC_XP0_OFF (16384 + 6144)
#define DEC_SMEM (DEC_XP0_OFF + 2048)

__global__ void __launch_bounds__(256, 1) dec_persist(float* __restrict__ out)
{
    extern __shared__ char smraw[];
    u64*   wsd  = (u64*)smraw;                      // [2][256][4] u64
    u64*   xch  = (u64*)(smraw + DEC_XCH_OFF);      // [3][4][64] u64
    float* xp0s = (float*)(smraw + DEC_XP0_OFF);    // [64][2][4] floats

    const int tid = threadIdx.x;
    const int ks  = tid >> 6;          // k-quarter 0..3 (64 k each)
    const int s   = tid & 63;
    const int l   = tid & 31;
    const int uu  = s >> 5;            // unit within CTA (warp-uniform)
    const int b0  = l * 2;
    const int f   = (int)blockIdx.x * 2 + uu;

    // load duplicated dec Whh slice once
    {
        const float4* src = (const float4*)&g_WdecHhDup[blockIdx.x * 2][0][0];
        float4* dst = (float4*)wsd;
        for (int i = tid; i < 1024; i += 256) dst[i] = src[i];
    }

    // ---- fused xp0 ----
    {
        const int fl = tid >> 7;
        const int gp = (tid >> 6) & 1;
        const int b  = tid & 63;
        const int ff = (int)blockIdx.x * 2 + fl;
        float a0 = 0.0f, a1 = 0.0f;
        const float* wih = &g_WdecIhIl[ff][0][gp * 2];
#pragma unroll 4
        for (int k = 0; k < 512; k++) {
            float hv = __ldg(&g_h[0][0][k][b]);
            float2 w2 = *(const float2*)&wih[k * 4];
            a0 += hv * w2.x; a1 += hv * w2.y;
        }
#pragma unroll 4
        for (int k = 0; k < 512; k++) {
            float hv = __ldg(&g_h[1][0][k][b]);
            float2 w2 = *(const float2*)&wih[(512 + k) * 4];
            a0 += hv * w2.x; a1 += hv * w2.y;
        }
        xp0s[(b * 2 + fl) * 4 + gp * 2 + 0] = a0 + g_bdecIl[ff][gp * 2 + 0];
        xp0s[(b * 2 + fl) * 4 + gp * 2 + 1] = a1 + g_bdecIl[ff][gp * 2 + 1];
    }
    __syncthreads();

    const u64* wp = wsd + uu * 1024;
    unsigned* cnt = g_cntd;
    float c0 = 0.f, c1 = 0.f;
    float4 xpA, xpB;
    if (ks == 0) {
        xpA = *(const float4*)&xp0s[(b0 * 2 + uu) * 4];
        xpB = *(const float4*)&xp0s[((b0 + 1) * 2 + uu) * 4];
    }

    for (int t = 0; t < T_; t++) {
        const int ph = t & 1;

        if (t > 0) {
            if (tid < 32) {
                const unsigned tgt = (unsigned)t * 128u;
                while (ld_acquire(cnt) < tgt) {}
            }
            __syncthreads();
        }

        const float* hbase = &g_hd[ph][0][0];
        const int kbase = ks * 64;

        u64 acc[4] = {0ull, 0ull, 0ull, 0ull};
#pragma unroll
        for (int blk = 0; blk < 4; blk++) {
            u64 hbuf[16];
#pragma unroll
            for (int j = 0; j < 16; j++)
                hbuf[j] = ldcg8(hbase + (kbase + blk * 16 + j) * 64 + b0);
#pragma unroll
            for (int j = 0; j < 16; j++) {
                const ulonglong2* wq = (const ulonglong2*)(wp + (kbase + blk * 16 + j) * 4);
                ulonglong2 w_if = wq[0], w_go = wq[1];
                fma2(acc[0], hbuf[j], w_if.x);
                fma2(acc[1], hbuf[j], w_if.y);
                fma2(acc[2], hbuf[j], w_go.x);
                fma2(acc[3], hbuf[j], w_go.y);
            }
        }

        if (ks > 0) {
            u64* dst = xch + (size_t)(ks - 1) * 4 * 64 + s;
            dst[0]   = acc[0];
            dst[64]  = acc[1];
            dst[128] = acc[2];
            dst[192] = acc[3];
        }
        __syncthreads();

        if (ks == 0) {
            const u64* src0 = xch + s;
#pragma unroll
            for (int r = 0; r < 3; r++) {
                const u64* src = src0 + (size_t)r * 4 * 64;
                acc[0] = add2(acc[0], src[0]);
                acc[1] = add2(acc[1], src[64]);
                acc[2] = add2(acc[2], src[128]);
                acc[3] = add2(acc[3], src[192]);
            }
            float2 iv = unpk(acc[0]), fv = unpk(acc[1]);
            float2 gv = unpk(acc[2]), ov = unpk(acc[3]);
            float2 hv;
            { float ig = sigm(iv.x + xpA.x), fg = sigm(fv.x + xpA.y);
              float gg = tanh_f(gv.x + xpA.z), og = sigm(ov.x + xpA.w);
              c0 = fg * c0 + ig * gg; hv.x = og * tanh_f(c0); }
            { float ig = sigm(iv.y + xpB.x), fg = sigm(fv.y + xpB.y);
              float gg = tanh_f(gv.y + xpB.z), og = sigm(ov.y + xpB.w);
              c1 = fg * c1 + ig * gg; hv.y = og * tanh_f(c1); }
            *(float2*)&g_hd[ph ^ 1][f][b0] = hv;
            out[((size_t)t * B_ + b0 + 0) * F_ + f] = hv.x;
            out[((size_t)t * B_ + b0 + 1) * F_ + f] = hv.y;
        }
        __syncthreads();

        if (tid == 0) red_release(cnt, 1u);
    }
}

// ---------------- launch ----------------
extern "C" void kernel_launch(void* const* d_in, const int* in_sizes, int n_in,
                              void* d_out, int out_size)
{
    const float* seq  = (const float*)d_in[0];
    const float* wihf = (const float*)d_in[1];
    const float* whhf = (const float*)d_in[2];
    const float* bf   = (const float*)d_in[3];
    const float* wihb = (const float*)d_in[4];
    const float* whhb = (const float*)d_in[5];
    const float* bb   = (const float*)d_in[6];
    const float* dwih = (const float*)d_in[7];
    const float* dwhh = (const float*)d_in[8];
    const float* db   = (const float*)d_in[9];
    float* out = (float*)d_out;

    cudaFuncSetAttribute(enc_persist, cudaFuncAttributeMaxDynamicSharedMemorySize, ENC_SMEM);
    cudaFuncSetAttribute(dec_persist, cudaFuncAttributeMaxDynamicSharedMemorySize, DEC_SMEM);

    probe_kernel<<<1, 1>>>();

    prep_kernel<<<1024, 256>>>(wihf, whhf, bf, wihb, whhb, bb, dwih, dwhh, db);

    dim3 g(G4E / 128, 32768 / 128, 2);
    xproj_gemm<<<g, 256>>>(seq);

    enc_persist<<<128, 256, ENC_SMEM>>>();

    dec_persist<<<128, 256, DEC_SMEM>>>(out);
}

// round 14
// speedup vs baseline: 1.2080x; 1.2080x over previous
#include <cuda_runtime.h>
#include <math.h>

// Problem dims
#define T_    512
#define B_    64
#define F_    256
#define E_    512
#define G4E   2048   // 4*E
#define G4F   1024   // 4*F
#define DECIN 1024   // 2*E

typedef unsigned long long u64;

// ---------------- device scratch (static; no allocations) ----------------
__device__ float g_xproj[2][T_][B_][G4E];     // [dir][t][b][col], col = u*4+gate
__device__ float g_WihIl[2][G4E][F_];         // interleaved enc Wih (rows = u*4+g)
__device__ float g_bIl[2][G4E];
__device__ float g_WhhIl[2][E_][E_][4];       // [dir][u][k][gate]
__device__ float g_h[2][2][E_][B_];           // [dir][phase][u][b]  ping-pong
__device__ float g_WdecIhIl[F_][DECIN][4];    // [f][k][gate]
__device__ float g_bdecIl[F_][4];
__device__ u64   g_WdecHhDup[F_][F_][4];      // [f][k][gate] duplicated {w,w}
__device__ float g_hd[2][F_][B_];             // decoder h ping-pong
__device__ unsigned g_cnt[2][32];             // enc barrier counters (padded per dir)
__device__ unsigned g_cntd[32];               // dec barrier counter

__device__ __forceinline__ float sigm(float x) {
    return __fdividef(1.0f, 1.0f + __expf(-x));
}
__device__ __forceinline__ float tanh_f(float x) {
    float ax = fabsf(x);
    float e = __expf(-2.0f * ax);
    float r = (1.0f - e) * __fdividef(1.0f, 1.0f + e);
    return copysignf(r, x);
}

__device__ __forceinline__ u64 dup2(float x) {
    u64 r; asm("mov.b64 %0, {%1, %1};" : "=l"(r) : "f"(x)); return r;
}
__device__ __forceinline__ void fma2(u64& d, u64 a, u64 b) {
    asm("fma.rn.f32x2 %0, %1, %2, %0;" : "+l"(d) : "l"(a), "l"(b));
}
__device__ __forceinline__ u64 add2(u64 a, u64 b) {
    u64 r; asm("add.rn.f32x2 %0, %1, %2;" : "=l"(r) : "l"(a), "l"(b)); return r;
}
__device__ __forceinline__ float2 unpk(u64 v) {
    float2 r; asm("mov.b64 {%0, %1}, %2;" : "=f"(r.x), "=f"(r.y) : "l"(v)); return r;
}
__device__ __forceinline__ unsigned ld_acquire(unsigned* p) {
    unsigned v;
    asm volatile("ld.acquire.gpu.global.u32 %0, [%1];" : "=r"(v) : "l"(p) : "memory");
    return v;
}
__device__ __forceinline__ void red_release(unsigned* p, unsigned v) {
    asm volatile("red.release.gpu.global.add.u32 [%0], %1;" :: "l"(p), "r"(v) : "memory");
}
__device__ __forceinline__ u64 ldcg8(const void* p) {
    u64 v;
    asm volatile("ld.global.cg.u64 %0, [%1];" : "=l"(v) : "l"(p));
    return v;
}
__device__ __forceinline__ void cp16(void* sdst, const void* gsrc) {
    unsigned s = (unsigned)__cvta_generic_to_shared(sdst);
    asm volatile("cp.async.cg.shared.global [%0], [%1], 16;" :: "r"(s), "l"(gsrc) : "memory");
}
__device__ __forceinline__ void cp_commit() { asm volatile("cp.async.commit_group;" ::: "memory"); }
template<int N> __device__ __forceinline__ void cp_wait() {
    asm volatile("cp.async.wait_group %0;" :: "n"(N) : "memory");
}

// ---------------- probe: keeps ncu's captured position stable ----------------
__global__ void probe_kernel() {}

// ---------------- prep: interleave weights, zero states ----------------
__global__ void prep_kernel(const float* wihf, const float* whhf, const float* bf,
                            const float* wihb, const float* whhb, const float* bb,
                            const float* dwih, const float* dwhh, const float* db)
{
    int tid = blockIdx.x * blockDim.x + threadIdx.x;
    int stride = gridDim.x * blockDim.x;

    // enc Wih interleave: [2][2048][256]
    for (int i = tid; i < 2 * G4E * F_; i += stride) {
        int d = i / (G4E * F_);
        int r = i - d * (G4E * F_);
        int col = r / F_;
        int k = r - col * F_;
        int u = col >> 2, g = col & 3;
        const float* src = d ? wihb : wihf;
        g_WihIl[d][col][k] = src[(g * E_ + u) * F_ + k];
    }
    // enc bias interleave
    for (int i = tid; i < 2 * G4E; i += stride) {
        int d = i >> 11, col = i & (G4E - 1);
        int u = col >> 2, g = col & 3;
        g_bIl[d][col] = (d ? bb : bf)[g * E_ + u];
    }
    // enc Whh interleave: [2][512][512][4]
    for (int i = tid; i < 2 * E_ * E_ * 4; i += stride) {
        int d = i / (E_ * E_ * 4);
        int r = i - d * (E_ * E_ * 4);
        int u = r / (E_ * 4);
        int k = (r >> 2) & (E_ - 1);
        int g = r & 3;
        g_WhhIl[d][u][k][g] = (d ? whhb : whhf)[(g * E_ + u) * E_ + k];
    }
    // dec Wih interleave: [256][1024][4]
    for (int i = tid; i < F_ * DECIN * 4; i += stride) {
        int f = i / (DECIN * 4);
        int k = (i >> 2) & (DECIN - 1);
        int g = i & 3;
        g_WdecIhIl[f][k][g] = dwih[(g * F_ + f) * DECIN + k];
    }
    for (int i = tid; i < G4F; i += stride) {
        int f = i >> 2, g = i & 3;
        g_bdecIl[f][g] = db[g * F_ + f];
    }
    // dec Whh duplicated: [256][256][4] u64
    for (int i = tid; i < F_ * F_ * 4; i += stride) {
        int f = i / (F_ * 4);
        int k = (i >> 2) & (F_ - 1);
        int g = i & 3;
        float v = dwhh[(g * F_ + f) * F_ + k];
        unsigned bits = __float_as_uint(v);
        g_WdecHhDup[f][k][g] = ((u64)bits << 32) | (u64)bits;
    }
    // zero states + counters
    for (int i = tid; i < 2 * 2 * E_ * B_; i += stride) ((float*)g_h)[i] = 0.0f;
    for (int i = tid; i < 2 * F_ * B_; i += stride)     ((float*)g_hd)[i] = 0.0f;
    if (tid < 64) ((unsigned*)g_cnt)[tid] = 0u;
    if (tid < 32) g_cntd[tid] = 0u;
}

// ---------------- xproj GEMM: M=32768, N=2048, K=256 ----------------
// Register double-buffer: next tile's LDG issued right after sync, hidden under compute.
__global__ void __launch_bounds__(256, 1) xproj_gemm(const float* __restrict__ seq)
{
    const int dir = blockIdx.z;
    const int m0 = blockIdx.y * 128;
    const int n0 = blockIdx.x * 128;
    const int tid = threadIdx.x;
    const int ty = tid >> 4;
    const int tx = tid & 15;

    __shared__ float As[16][128];
    __shared__ float Bs[16][128];

    u64 acc[8][4];
#pragma unroll
    for (int i = 0; i < 8; i++)
#pragma unroll
        for (int j = 0; j < 4; j++) acc[i][j] = 0ull;

    const float* W = &g_WihIl[dir][0][0];

    int arow[2], akq[2], nidx[2], bkq[2];
    const float* aptr[2];
#pragma unroll
    for (int p = 0; p < 2; p++) {
        int idx = tid + p * 256;
        arow[p] = idx >> 2; akq[p] = idx & 3;
        int m = m0 + arow[p];
        int tt = m >> 6, b = m & 63;
        int ts = dir ? (T_ - 1 - tt) : tt;
        aptr[p] = &seq[((size_t)ts * B_ + b) * F_];
        nidx[p] = idx >> 2; bkq[p] = idx & 3;
    }

    float4 ra[2], rb[2];
#pragma unroll
    for (int p = 0; p < 2; p++) {
        ra[p] = *(const float4*)&aptr[p][akq[p] * 4];
        rb[p] = *(const float4*)&W[(size_t)(n0 + nidx[p]) * F_ + bkq[p] * 4];
    }

    for (int k0 = 0; k0 < F_; k0 += 16) {
#pragma unroll
        for (int p = 0; p < 2; p++) {
            As[akq[p] * 4 + 0][arow[p]] = ra[p].x;
            As[akq[p] * 4 + 1][arow[p]] = ra[p].y;
            As[akq[p] * 4 + 2][arow[p]] = ra[p].z;
            As[akq[p] * 4 + 3][arow[p]] = ra[p].w;
            Bs[bkq[p] * 4 + 0][nidx[p]] = rb[p].x;
            Bs[bkq[p] * 4 + 1][nidx[p]] = rb[p].y;
            Bs[bkq[p] * 4 + 2][nidx[p]] = rb[p].z;
            Bs[bkq[p] * 4 + 3][nidx[p]] = rb[p].w;
        }
        __syncthreads();

        if (k0 + 16 < F_) {
#pragma unroll
            for (int p = 0; p < 2; p++) {
                ra[p] = *(const float4*)&aptr[p][k0 + 16 + akq[p] * 4];
                rb[p] = *(const float4*)&W[(size_t)(n0 + nidx[p]) * F_ + k0 + 16 + bkq[p] * 4];
            }
        }

#pragma unroll
        for (int kk = 0; kk < 16; kk++) {
            float4 a0 = *(const float4*)&As[kk][ty * 8];
            float4 a1 = *(const float4*)&As[kk][ty * 8 + 4];
            ulonglong2 bA = *(const ulonglong2*)&Bs[kk][tx * 4];
            ulonglong2 bB = *(const ulonglong2*)&Bs[kk][64 + tx * 4];
            float av[8] = {a0.x, a0.y, a0.z, a0.w, a1.x, a1.y, a1.z, a1.w};
#pragma unroll
            for (int i = 0; i < 8; i++) {
                u64 ad = dup2(av[i]);
                fma2(acc[i][0], ad, bA.x);
                fma2(acc[i][1], ad, bA.y);
                fma2(acc[i][2], ad, bB.x);
                fma2(acc[i][3], ad, bB.y);
            }
        }
        __syncthreads();
    }

    float4 bias0 = *(const float4*)&g_bIl[dir][n0 + tx * 4];
    float4 bias1 = *(const float4*)&g_bIl[dir][n0 + 64 + tx * 4];
    float* out = &g_xproj[0][0][0][0];
#pragma unroll
    for (int i = 0; i < 8; i++) {
        size_t m = (size_t)m0 + ty * 8 + i;
        size_t base = ((size_t)dir * 32768 + m) * (size_t)G4E + n0;
        float2 c0 = unpk(acc[i][0]), c1 = unpk(acc[i][1]);
        float2 c2 = unpk(acc[i][2]), c3 = unpk(acc[i][3]);
        float4 o0 = {c0.x + bias0.x, c0.y + bias0.y, c1.x + bias0.z, c1.y + bias0.w};
        float4 o1 = {c2.x + bias1.x, c2.y + bias1.y, c3.x + bias1.z, c3.y + bias1.w};
        *(float4*)&out[base + tx * 4] = o0;
        *(float4*)&out[base + 64 + tx * 4] = o1;
    }
}

// ---------------- persistent encoder ----------------
// 128 CTAs (64/dir, 8 units each), 256 threads = 8 warps; warp = 64-k slice.
// Lane = (unit-group l&1)x(batch-group l>>1); thread = 4 units x 4 batches.
// Per thread-k: 1 h-LDS.128 (pair-shared, 2wf) + 4 w-LDS.128 (2-addr bcast, 1wf)
// for 128 MACs -> CTA LDS wavefronts ~3K/step << fma floor ~8K cyc -> fma-bound.
// Reduction: all warps publish into xch (aliases dead hs region), then fully
// distributed reduce+epilogue: thread = (unit w, batch-pair l).
#define ENC_HS_OFF  65536                    // ws: [512][8] float4 = 64KB
#define ENC_XPS_OFF (65536 + 131072)         // hs: [512][64] float = 128KB (xch aliased)
#define ENC_SMEM    (ENC_XPS_OFF + 8192)     // xps: [64][8] float4 = 8KB -> 204800

__global__ void __launch_bounds__(256, 1) enc_persist()
{
    extern __shared__ char smraw[];
    float4* wsP = (float4*)smraw;                    // [k][8 units]
    float*  hs  = (float*)(smraw + ENC_HS_OFF);      // [512][64]
    u64*    xch = (u64*)(smraw + ENC_HS_OFF);        // aliases hs; used post-compute (64KB)
    float4* xps = (float4*)(smraw + ENC_XPS_OFF);    // [64 b][8 u]

    const int dir = (int)(blockIdx.x >> 6);
    const int u0  = (int)(blockIdx.x & 63) * 8;
    const int tid = threadIdx.x;
    const int w   = tid >> 5;          // warp = k-slice 0..7 (also epilogue unit)
    const int l   = tid & 31;
    const int ug  = l & 1;             // unit group: units ug*4..ug*4+3
    const int bg  = l >> 1;            // batch group: batches bg*4..bg*4+3
    const int kbase = w * 64;

    // load Whh slice once, transposed to k-major [k][u]
    {
        const float4* src = (const float4*)&g_WhhIl[dir][u0][0][0];
        for (int i = tid; i < 4096; i += 256)
            wsP[i] = src[(i & 7) * 512 + (i >> 3)];
    }
    __syncthreads();

    unsigned* cnt = &g_cnt[dir][0];
    float c0 = 0.0f, c1 = 0.0f;   // epilogue state: (unit w, batches 2l, 2l+1)

    // stage xproj for t=0
    for (int i = tid; i < 512; i += 256)
        cp16(&xps[i], &g_xproj[dir][0][i >> 3][(u0 + (i & 7)) << 2]);
    cp_commit();

    for (int t = 0; t < T_; t++) {
        const int ph = t & 1;

        // wait for h(t-1) from all CTAs of this dir
        if (t > 0) {
            if (tid < 32) {
                const unsigned tgt = (unsigned)t * 64u;
                while (ld_acquire(cnt) < tgt) {}
            }
            __syncthreads();
        }

        // stage this warp's 64-k slice (1024 float4) in 2 pipelined halves
        {
            const float4* hsrc = (const float4*)&g_h[dir][ph][kbase][0];
            float4* hdst = (float4*)&hs[kbase * 64];
            for (int i = l; i < 512; i += 32) cp16(hdst + i, hsrc + i);
            cp_commit();
            for (int i = 512 + l; i < 1024; i += 32) cp16(hdst + i, hsrc + i);
            cp_commit();
        }
        // pending groups: [xps][h1][h2]

        u64 acc[4][4][2];   // [unit j][gate][batch-pair]
#pragma unroll
        for (int j = 0; j < 4; j++)
#pragma unroll
            for (int g = 0; g < 4; g++) { acc[j][g][0] = 0ull; acc[j][g][1] = 0ull; }

#pragma unroll
        for (int half = 0; half < 2; half++) {
            if (half == 0) cp_wait<1>(); else cp_wait<0>();
            __syncwarp();
            const int kst = kbase + half * 32;
#pragma unroll 4
            for (int kk = 0; kk < 32; kk++) {
                const int k = kst + kk;
                ulonglong2 hq = *(const ulonglong2*)(hs + k * 64 + (bg << 2));
                const float4* wrow = wsP + k * 8 + (ug << 2);
#pragma unroll
                for (int j = 0; j < 4; j++) {
                    float4 wv = wrow[j];
                    u64 d0 = dup2(wv.x), d1 = dup2(wv.y), d2 = dup2(wv.z), d3 = dup2(wv.w);
                    fma2(acc[j][0][0], hq.x, d0); fma2(acc[j][0][1], hq.y, d0);
                    fma2(acc[j][1][0], hq.x, d1); fma2(acc[j][1][1], hq.y, d1);
                    fma2(acc[j][2][0], hq.x, d2); fma2(acc[j][2][1], hq.y, d2);
                    fma2(acc[j][3][0], hq.x, d3); fma2(acc[j][3][1], hq.y, d3);
                }
            }
        }
        __syncthreads();   // all hs reads complete before aliasing writes

        // publish: all 8 warps, STS.128, layout [w][j][g][lane][p]
#pragma unroll
        for (int j = 0; j < 4; j++)
#pragma unroll
            for (int g = 0; g < 4; g++)
                *(ulonglong2*)(xch + (size_t)(((w * 16 + j * 4 + g) * 32) + l) * 2)
                    = make_ulonglong2(acc[j][g][0], acc[j][g][1]);
        __syncthreads();

        // distributed reduce + epilogue: thread -> (unit w, batches 2l, 2l+1)
        {
            const int j    = w & 3;
            const int lsrc = ((l >> 1) << 1) + (w >> 2);
            const int p    = l & 1;
            u64 v[4];
#pragma unroll
            for (int g = 0; g < 4; g++) {
                u64 s = xch[(size_t)(((j * 4 + g) * 32) + lsrc) * 2 + p];
#pragma unroll
                for (int r = 1; r < 8; r++)
                    s = add2(s, xch[(size_t)((((r * 16 + j * 4 + g) * 32) + lsrc)) * 2 + p]);
                v[g] = s;
            }
            float2 iv = unpk(v[0]), fv = unpk(v[1]);
            float2 gv = unpk(v[2]), ov = unpk(v[3]);
            const int b = l * 2;
            float4 xA = xps[b * 8 + w];
            float4 xB = xps[(b + 1) * 8 + w];
            float2 hv;
            { float ig = sigm(iv.x + xA.x), fg = sigm(fv.x + xA.y);
              float gg = tanh_f(gv.x + xA.z), og = sigm(ov.x + xA.w);
              c0 = fg * c0 + ig * gg; hv.x = og * tanh_f(c0); }
            { float ig = sigm(iv.y + xB.x), fg = sigm(fv.y + xB.y);
              float gg = tanh_f(gv.y + xB.z), og = sigm(ov.y + xB.w);
              c1 = fg * c1 + ig * gg; hv.y = og * tanh_f(c1); }
            *(float2*)&g_h[dir][ph ^ 1][u0 + w][b] = hv;
        }
        __syncthreads();

        // arrive; then stage next step's xproj (overlaps barrier propagation)
        if (tid == 0) red_release(cnt, 1u);
        if (t + 1 < T_) {
            for (int i = tid; i < 512; i += 256)
                cp16(&xps[i], &g_xproj[dir][t + 1][i >> 3][(u0 + (i & 7)) << 2]);
            cp_commit();
        }
    }
}

// ---------------- persistent decoder (xp0 fused) ----------------
#define DEC_XCH_OFF 16384
#define DEC_XP0_OFF (16384 + 6144)
#define DEC_SMEM (DEC_XP0_OFF + 2048)

__global__ void __launch_bounds__(256, 1) dec_persist(float* __restrict__ out)
{
    extern __shared__ char smraw[];
    u64*   wsd  = (u64*)smraw;                      // [2][256][4] u64
    u64*   xch  = (u64*)(smraw + DEC_XCH_OFF);      // [3][4][64] u64
    float* xp0s = (float*)(smraw + DEC_XP0_OFF);    // [64][2][4] floats

    const int tid = threadIdx.x;
    const int ks  = tid >> 6;          // k-quarter 0..3 (64 k each)
    const int s   = tid & 63;
    const int l   = tid & 31;
    const int uu  = s >> 5;            // unit within CTA (warp-uniform)
    const int b0  = l * 2;
    const int f   = (int)blockIdx.x * 2 + uu;

    // load duplicated dec Whh slice once
    {
        const float4* src = (const float4*)&g_WdecHhDup[blockIdx.x * 2][0][0];
        float4* dst = (float4*)wsd;
        for (int i = tid; i < 1024; i += 256) dst[i] = src[i];
    }

    // ---- fused xp0 ----
    {
        const int fl = tid >> 7;
        const int gp = (tid >> 6) & 1;
        const int b  = tid & 63;
        const int ff = (int)blockIdx.x * 2 + fl;
        float a0 = 0.0f, a1 = 0.0f;
        const float* wih = &g_WdecIhIl[ff][0][gp * 2];
#pragma unroll 4
        for (int k = 0; k < 512; k++) {
            float hv = __ldg(&g_h[0][0][k][b]);
            float2 w2 = *(const float2*)&wih[k * 4];
            a0 += hv * w2.x; a1 += hv * w2.y;
        }
#pragma unroll 4
        for (int k = 0; k < 512; k++) {
            float hv = __ldg(&g_h[1][0][k][b]);
            float2 w2 = *(const float2*)&wih[(512 + k) * 4];
            a0 += hv * w2.x; a1 += hv * w2.y;
        }
        xp0s[(b * 2 + fl) * 4 + gp * 2 + 0] = a0 + g_bdecIl[ff][gp * 2 + 0];
        xp0s[(b * 2 + fl) * 4 + gp * 2 + 1] = a1 + g_bdecIl[ff][gp * 2 + 1];
    }
    __syncthreads();

    const u64* wp = wsd + uu * 1024;
    unsigned* cnt = g_cntd;
    float c0 = 0.f, c1 = 0.f;
    float4 xpA, xpB;
    if (ks == 0) {
        xpA = *(const float4*)&xp0s[(b0 * 2 + uu) * 4];
        xpB = *(const float4*)&xp0s[((b0 + 1) * 2 + uu) * 4];
    }

    for (int t = 0; t < T_; t++) {
        const int ph = t & 1;

        if (t > 0) {
            if (tid < 32) {
                const unsigned tgt = (unsigned)t * 128u;
                while (ld_acquire(cnt) < tgt) {}
            }
            __syncthreads();
        }

        const float* hbase = &g_hd[ph][0][0];
        const int kbase = ks * 64;

        u64 acc[4] = {0ull, 0ull, 0ull, 0ull};
#pragma unroll
        for (int blk = 0; blk < 4; blk++) {
            u64 hbuf[16];
#pragma unroll
            for (int j = 0; j < 16; j++)
                hbuf[j] = ldcg8(hbase + (kbase + blk * 16 + j) * 64 + b0);
#pragma unroll
            for (int j = 0; j < 16; j++) {
                const ulonglong2* wq = (const ulonglong2*)(wp + (kbase + blk * 16 + j) * 4);
                ulonglong2 w_if = wq[0], w_go = wq[1];
                fma2(acc[0], hbuf[j], w_if.x);
                fma2(acc[1], hbuf[j], w_if.y);
                fma2(acc[2], hbuf[j], w_go.x);
                fma2(acc[3], hbuf[j], w_go.y);
            }
        }

        if (ks > 0) {
            u64* dst = xch + (size_t)(ks - 1) * 4 * 64 + s;
            dst[0]   = acc[0];
            dst[64]  = acc[1];
            dst[128] = acc[2];
            dst[192] = acc[3];
        }
        __syncthreads();

        if (ks == 0) {
            const u64* src0 = xch + s;
#pragma unroll
            for (int r = 0; r < 3; r++) {
                const u64* src = src0 + (size_t)r * 4 * 64;
                acc[0] = add2(acc[0], src[0]);
                acc[1] = add2(acc[1], src[64]);
                acc[2] = add2(acc[2], src[128]);
                acc[3] = add2(acc[3], src[192]);
            }
            float2 iv = unpk(acc[0]), fv = unpk(acc[1]);
            float2 gv = unpk(acc[2]), ov = unpk(acc[3]);
            float2 hv;
            { float ig = sigm(iv.x + xpA.x), fg = sigm(fv.x + xpA.y);
              float gg = tanh_f(gv.x + xpA.z), og = sigm(ov.x + xpA.w);
              c0 = fg * c0 + ig * gg; hv.x = og * tanh_f(c0); }
            { float ig = sigm(iv.y + xpB.x), fg = sigm(fv.y + xpB.y);
              float gg = tanh_f(gv.y + xpB.z), og = sigm(ov.y + xpB.w);
              c1 = fg * c1 + ig * gg; hv.y = og * tanh_f(c1); }
            *(float2*)&g_hd[ph ^ 1][f][b0] = hv;
            out[((size_t)t * B_ + b0 + 0) * F_ + f] = hv.x;
            out[((size_t)t * B_ + b0 + 1) * F_ + f] = hv.y;
        }
        __syncthreads();

        if (tid == 0) red_release(cnt, 1u);
    }
}

// ---------------- launch ----------------
extern "C" void kernel_launch(void* const* d_in, const int* in_sizes, int n_in,
                              void* d_out, int out_size)
{
    const float* seq  = (const float*)d_in[0];
    const float* wihf = (const float*)d_in[1];
    const float* whhf = (const float*)d_in[2];
    const float* bf   = (const float*)d_in[3];
    const float* wihb = (const float*)d_in[4];
    const float* whhb = (const float*)d_in[5];
    const float* bb   = (const float*)d_in[6];
    const float* dwih = (const float*)d_in[7];
    const float* dwhh = (const float*)d_in[8];
    const float* db   = (const float*)d_in[9];
    float* out = (float*)d_out;

    cudaFuncSetAttribute(enc_persist, cudaFuncAttributeMaxDynamicSharedMemorySize, ENC_SMEM);
    cudaFuncSetAttribute(dec_persist, cudaFuncAttributeMaxDynamicSharedMemorySize, DEC_SMEM);

    probe_kernel<<<1, 1>>>();

    prep_kernel<<<1024, 256>>>(wihf, whhf, bf, wihb, whhb, bb, dwih, dwhh, db);

    dim3 g(G4E / 128, 32768 / 128, 2);
    xproj_gemm<<<g, 256>>>(seq);

    enc_persist<<<128, 256, ENC_SMEM>>>();

    dec_persist<<<128, 256, DEC_SMEM>>>(out);
}